// round 10
// baseline (speedup 1.0000x reference)
#include <cuda_runtime.h>
#include <cuda_bf16.h>
#include <cstdint>

#define B_  64
#define D_  128
#define LC  1024
#define LQ  256
#define LDS_ 40      // smem row stride in bf16 elements (conflict-free for ldmatrix)

// ---------------- scratch (static device arrays) ----------------
static __device__ float g_E   [(size_t)B_*LC*LQ];    // exp(S + biases), unnormalized
static __device__ float g_T   [(size_t)B_*LQ*D_];    // T_raw [m'][d] (unscaled)
static __device__ float g_rinv[B_*LC];
static __device__ float g_qcinv[B_*LQ];
static __device__ float g_cpart[B_*8*LQ];
static __device__ float g_c1[B_*LC];
static __device__ float g_q2[B_*LQ];

// ---------------- helpers ----------------
__device__ __forceinline__ uint32_t smem_u32(const void* p) {
    uint32_t a;
    asm("{ .reg .u64 t; cvta.to.shared.u64 t, %1; cvt.u32.u64 %0, t; }" : "=r"(a) : "l"(p));
    return a;
}

#define LDSM_X4(r, a) \
    asm volatile("ldmatrix.sync.aligned.m8n8.x4.shared.b16 {%0,%1,%2,%3}, [%4];" \
        : "=r"((r)[0]), "=r"((r)[1]), "=r"((r)[2]), "=r"((r)[3]) : "r"(a))

#define MMA_BF16(c, a, b0, b1) \
    asm volatile("mma.sync.aligned.m16n8k16.row.col.f32.bf16.bf16.f32 " \
        "{%0,%1,%2,%3}, {%4,%5,%6,%7}, {%8,%9}, {%0,%1,%2,%3};" \
        : "+f"((c)[0]), "+f"((c)[1]), "+f"((c)[2]), "+f"((c)[3]) \
        : "r"((a)[0]), "r"((a)[1]), "r"((a)[2]), "r"((a)[3]), "r"(b0), "r"(b1))

__device__ __forceinline__ void cvt4(const float4& x, uint2& uh, uint2& ul) {
    __nv_bfloat16 hx = __float2bfloat16(x.x), hy = __float2bfloat16(x.y);
    __nv_bfloat16 hz = __float2bfloat16(x.z), hw = __float2bfloat16(x.w);
    __nv_bfloat162 h01(hx, hy), h23(hz, hw);
    __nv_bfloat162 l01(__float2bfloat16(x.x - __bfloat162float(hx)),
                       __float2bfloat16(x.y - __bfloat162float(hy)));
    __nv_bfloat162 l23(__float2bfloat16(x.z - __bfloat162float(hz)),
                       __float2bfloat16(x.w - __bfloat162float(hw)));
    uh.x = *reinterpret_cast<uint32_t*>(&h01); uh.y = *reinterpret_cast<uint32_t*>(&h23);
    ul.x = *reinterpret_cast<uint32_t*>(&l01); ul.y = *reinterpret_cast<uint32_t*>(&l23);
}

// ---------------- generic tgemm (G1, G3) ----------------
template<bool TRANS, bool KS>
__device__ __forceinline__ void ldg_op(const float* __restrict__ src, int ld, int mn0,
                                       int kk, const float* __restrict__ ks,
                                       int tid, float4 (&r)[4]) {
#pragma unroll
    for (int i = 0; i < 4; i++) {
        int v = i * 256 + tid;
        if constexpr (!TRANS) {
            int row = v >> 3, c4 = v & 7;
            float4 x = *reinterpret_cast<const float4*>(src + (size_t)(mn0 + row) * ld + kk + c4 * 4);
            if constexpr (KS) {
                float4 s = *reinterpret_cast<const float4*>(ks + kk + c4 * 4);
                x.x *= s.x; x.y *= s.y; x.z *= s.z; x.w *= s.w;
            }
            r[i] = x;
        } else {
            int mn = v & 127, krb = v >> 7;
            const float* p = src + (size_t)(kk + krb * 4) * ld + mn0 + mn;
            float4 x;
            x.x = p[0]; x.y = p[ld]; x.z = p[2 * (size_t)ld]; x.w = p[3 * (size_t)ld];
            if constexpr (KS) {
                const float* s = ks + kk + krb * 4;
                x.x *= s[0]; x.y *= s[1]; x.z *= s[2]; x.w *= s[3];
            }
            r[i] = x;
        }
    }
}

template<bool TRANS>
__device__ __forceinline__ void sts_op(float4 (&r)[4], __nv_bfloat16* smh, __nv_bfloat16* sml, int tid) {
#pragma unroll
    for (int i = 0; i < 4; i++) {
        int v = i * 256 + tid;
        int off;
        if constexpr (!TRANS) { int row = v >> 3, c4 = v & 7; off = row * LDS_ + c4 * 4; }
        else                  { int mn = v & 127, krb = v >> 7; off = mn * LDS_ + krb * 4; }
        uint2 uh, ul;
        cvt4(r[i], uh, ul);
        *reinterpret_cast<uint2*>(smh + off) = uh;
        *reinterpret_cast<uint2*>(sml + off) = ul;
    }
}

// EPI 0: plain fp32 ; EPI 1: exp(acc + biasR[row] + biasC[col])
// double-buffered smem: 2 buffers x 4 planes x 128*LDS_ bf16 = 81920 B dynamic
template<bool AT, bool BT, bool KSA, bool KSB, int EPI>
__global__ __launch_bounds__(256) void tgemm(
    const float* __restrict__ Ag, int lda, long batA,
    const float* __restrict__ Bg, int ldb, long batB,
    float* __restrict__ Cg, int ldc, long batC,
    int Kloc,
    const float* __restrict__ ksA, int ksAstr,
    const float* __restrict__ ksB, int ksBstr,
    const float* __restrict__ biasR, const float* __restrict__ biasC)
{
    extern __shared__ __align__(16) __nv_bfloat16 smb[];
    const int PLANE = 128 * LDS_;              // 5120 elems, 10240 B

    const int zb = blockIdx.z;
    const int m0 = blockIdx.y << 7;
    const int n0 = blockIdx.x << 7;
    const float* Ab = Ag + (size_t)zb * batA;
    const float* Bb = Bg + (size_t)zb * batB;
    const float* kA = KSA ? (ksA + (size_t)zb * ksAstr) : nullptr;
    const float* kB = KSB ? (ksB + (size_t)zb * ksBstr) : nullptr;

    const int tid = threadIdx.x, wid = tid >> 5, lane = tid & 31;
    const int wm = (wid >> 2) * 64, wn = (wid & 3) * 32;

    float acc[4][4][4];
#pragma unroll
    for (int i = 0; i < 4; i++)
#pragma unroll
        for (int j = 0; j < 4; j++)
#pragma unroll
            for (int e = 0; e < 4; e++) acc[i][j][e] = 0.f;

    float4 ra[4], rb[4];
    const uint32_t smbase = smem_u32(smb);

    const int nch = Kloc >> 5;
    ldg_op<AT, KSA>(Ab, lda, m0, 0, kA, tid, ra);
    ldg_op<BT, KSB>(Bb, ldb, n0, 0, kB, tid, rb);
    sts_op<AT>(ra, smb, smb + PLANE, tid);
    sts_op<BT>(rb, smb + 2 * PLANE, smb + 3 * PLANE, tid);
    __syncthreads();

    for (int ch = 0; ch < nch; ch++) {
        if (ch + 1 < nch) {
            int kk = (ch + 1) << 5;
            ldg_op<AT, KSA>(Ab, lda, m0, kk, kA, tid, ra);
            ldg_op<BT, KSB>(Bb, ldb, n0, kk, kB, tid, rb);
        }
        const uint32_t sb = smbase + (uint32_t)(ch & 1) * 40960u;
        const uint32_t bAh = sb, bAl = sb + 10240u, bBh = sb + 20480u, bBl = sb + 30720u;
#pragma unroll
        for (int ks = 0; ks < 2; ks++) {
            uint32_t afh[4][4], afl[4][4];
#pragma unroll
            for (int mt = 0; mt < 4; mt++) {
                uint32_t aoff = (uint32_t)((wm + mt * 16 + (lane & 15)) * LDS_
                                           + ks * 16 + ((lane >> 4) << 3)) * 2u;
                LDSM_X4(afh[mt], bAh + aoff);
                LDSM_X4(afl[mt], bAl + aoff);
            }
            uint32_t bfh[2][4], bfl[2][4];
#pragma unroll
            for (int nt = 0; nt < 2; nt++) {
                uint32_t boff = (uint32_t)((wn + nt * 16 + ((lane >> 4) << 3) + (lane & 7)) * LDS_
                                           + ks * 16 + (((lane >> 3) & 1) << 3)) * 2u;
                LDSM_X4(bfh[nt], bBh + boff);
                LDSM_X4(bfl[nt], bBl + boff);
            }
#pragma unroll
            for (int mt = 0; mt < 4; mt++)
#pragma unroll
                for (int nt = 0; nt < 2; nt++)
#pragma unroll
                    for (int h = 0; h < 2; h++) {
                        float* c = acc[mt][nt * 2 + h];
                        MMA_BF16(c, afh[mt], bfh[nt][2 * h], bfh[nt][2 * h + 1]);
                        MMA_BF16(c, afh[mt], bfl[nt][2 * h], bfl[nt][2 * h + 1]);
                        MMA_BF16(c, afl[mt], bfh[nt][2 * h], bfh[nt][2 * h + 1]);
                    }
        }
        if (ch + 1 < nch) {
            __nv_bfloat16* nb = smb + ((ch + 1) & 1) * 4 * PLANE;
            sts_op<AT>(ra, nb, nb + PLANE, tid);
            sts_op<BT>(rb, nb + 2 * PLANE, nb + 3 * PLANE, tid);
            __syncthreads();
        }
    }

    float* Cb = Cg + (size_t)zb * batC;
#pragma unroll
    for (int mt = 0; mt < 4; mt++) {
        int r0 = m0 + wm + mt * 16 + (lane >> 2);
        int r1 = r0 + 8;
        float br0 = 0.f, br1 = 0.f;
        if constexpr (EPI == 1) { br0 = biasR[zb * LC + r0]; br1 = biasR[zb * LC + r1]; }
#pragma unroll
        for (int nt = 0; nt < 4; nt++) {
            int col = n0 + wn + nt * 8 + (lane & 3) * 2;
            float2 v0, v1;
            v0.x = acc[mt][nt][0]; v0.y = acc[mt][nt][1];
            v1.x = acc[mt][nt][2]; v1.y = acc[mt][nt][3];
            if constexpr (EPI == 1) {
                float bc0 = biasC[zb * LQ + col], bc1 = biasC[zb * LQ + col + 1];
                v0.x = __expf(v0.x + br0 + bc0); v0.y = __expf(v0.y + br0 + bc1);
                v1.x = __expf(v1.x + br1 + bc0); v1.y = __expf(v1.y + br1 + bc1);
            }
            *reinterpret_cast<float2*>(Cb + (size_t)r0 * ldc + col) = v0;
            *reinterpret_cast<float2*>(Cb + (size_t)r1 * ldc + col) = v1;
        }
    }
}

// ---------------- fused G2+G4: stacked A = [Q*qm ; T_raw*qcinv], B = E tile ----------------
// double-buffered: buffer = sAh(256*LDS_) sAl sBh(64*LDS_) sBl = 51200 B; x2 = 102400 B
__global__ __launch_bounds__(256) void g24(
    const float* __restrict__ Q, const float* __restrict__ T,
    const float* __restrict__ E, const float* __restrict__ C,
    const float* __restrict__ qmask, const float* __restrict__ qcinv,
    const float* __restrict__ rinv, float* __restrict__ out)
{
    extern __shared__ __align__(16) __nv_bfloat16 smb[];
    const int PA = 256 * LDS_;    // 10240 elems
    const int PB = 64 * LDS_;     // 2560 elems
    const int BUFE = 2 * PA + 2 * PB;   // 25600 elems = 51200 B

    const int zb = blockIdx.z;
    const int n0 = blockIdx.x * 64;
    const float* Qb = Q + (size_t)zb * D_ * LQ;
    const float* Tb = T + (size_t)zb * LQ * D_;
    const float* Eb = E + (size_t)zb * LC * LQ;
    const float* qm = qmask + zb * LQ;
    const float* qc = qcinv + zb * LQ;

    const int tid = threadIdx.x, wid = tid >> 5, lane = tid & 31;
    const int wm = (wid >> 1) * 64, wn = (wid & 1) * 32;

    float acc[4][4][4];
#pragma unroll
    for (int i = 0; i < 4; i++)
#pragma unroll
        for (int j = 0; j < 4; j++)
#pragma unroll
            for (int e = 0; e < 4; e++) acc[i][j][e] = 0.f;

    float4 ra[8], rb[2];

    auto ldgA = [&](int kk) {
#pragma unroll
        for (int i = 0; i < 4; i++) {                 // Q half, rows 0..127, K-fast
            int v = i * 256 + tid;
            int row = v >> 3, c4 = v & 7;
            float4 x = *reinterpret_cast<const float4*>(Qb + (size_t)row * LQ + kk + c4 * 4);
            float4 s = *reinterpret_cast<const float4*>(qm + kk + c4 * 4);
            x.x *= s.x; x.y *= s.y; x.z *= s.z; x.w *= s.w;
            ra[i] = x;
        }
#pragma unroll
        for (int i = 0; i < 4; i++) {                 // T half, rows 128..255, K-slow
            int v = i * 256 + tid;
            int mn = v & 127, krb = v >> 7;
            const float* p = Tb + (size_t)(kk + krb * 4) * D_ + mn;
            const float* s = qc + kk + krb * 4;
            float4 x;
            x.x = p[0] * s[0]; x.y = p[D_] * s[1];
            x.z = p[2 * D_] * s[2]; x.w = p[3 * D_] * s[3];
            ra[4 + i] = x;
        }
    };
    auto ldgB = [&](int kk) {
#pragma unroll
        for (int i = 0; i < 2; i++) {                 // E tile, 64 rows (l), K-fast
            int v = i * 256 + tid;
            int row = v >> 3, c4 = v & 7;
            rb[i] = *reinterpret_cast<const float4*>(Eb + (size_t)(n0 + row) * LQ + kk + c4 * 4);
        }
    };
    auto sts = [&](int buf) {
        __nv_bfloat16* sAh = smb + buf * BUFE;
        __nv_bfloat16* sAl = sAh + PA;
        __nv_bfloat16* sBh = sAl + PA;
        __nv_bfloat16* sBl = sBh + PB;
#pragma unroll
        for (int i = 0; i < 4; i++) {
            int v = i * 256 + tid;
            int row = v >> 3, c4 = v & 7;
            uint2 uh, ul; cvt4(ra[i], uh, ul);
            int off = row * LDS_ + c4 * 4;
            *reinterpret_cast<uint2*>(sAh + off) = uh;
            *reinterpret_cast<uint2*>(sAl + off) = ul;
        }
#pragma unroll
        for (int i = 0; i < 4; i++) {
            int v = i * 256 + tid;
            int mn = v & 127, krb = v >> 7;
            uint2 uh, ul; cvt4(ra[4 + i], uh, ul);
            int off = (128 + mn) * LDS_ + krb * 4;
            *reinterpret_cast<uint2*>(sAh + off) = uh;
            *reinterpret_cast<uint2*>(sAl + off) = ul;
        }
#pragma unroll
        for (int i = 0; i < 2; i++) {
            int v = i * 256 + tid;
            int row = v >> 3, c4 = v & 7;
            uint2 uh, ul; cvt4(rb[i], uh, ul);
            int off = row * LDS_ + c4 * 4;
            *reinterpret_cast<uint2*>(sBh + off) = uh;
            *reinterpret_cast<uint2*>(sBl + off) = ul;
        }
    };

    const uint32_t smbase = smem_u32(smb);

    const int nch = LQ >> 5;   // 8
    ldgA(0); ldgB(0);
    sts(0);
    __syncthreads();

    for (int ch = 0; ch < nch; ch++) {
        if (ch + 1 < nch) { ldgA((ch + 1) << 5); ldgB((ch + 1) << 5); }
        const uint32_t sb = smbase + (uint32_t)(ch & 1) * (BUFE * 2u);
        const uint32_t bAh = sb, bAl = sb + PA * 2u;
        const uint32_t bBh = sb + 2u * PA * 2u, bBl = sb + (2u * PA + PB) * 2u;
#pragma unroll
        for (int ks = 0; ks < 2; ks++) {
            uint32_t afh[4][4], afl[4][4];
#pragma unroll
            for (int mt = 0; mt < 4; mt++) {
                uint32_t aoff = (uint32_t)((wm + mt * 16 + (lane & 15)) * LDS_
                                           + ks * 16 + ((lane >> 4) << 3)) * 2u;
                LDSM_X4(afh[mt], bAh + aoff);
                LDSM_X4(afl[mt], bAl + aoff);
            }
            uint32_t bfh[2][4], bfl[2][4];
#pragma unroll
            for (int nt = 0; nt < 2; nt++) {
                uint32_t boff = (uint32_t)((wn + nt * 16 + ((lane >> 4) << 3) + (lane & 7)) * LDS_
                                           + ks * 16 + (((lane >> 3) & 1) << 3)) * 2u;
                LDSM_X4(bfh[nt], bBh + boff);
                LDSM_X4(bfl[nt], bBl + boff);
            }
#pragma unroll
            for (int mt = 0; mt < 4; mt++)
#pragma unroll
                for (int nt = 0; nt < 2; nt++)
#pragma unroll
                    for (int h = 0; h < 2; h++) {
                        float* c = acc[mt][nt * 2 + h];
                        MMA_BF16(c, afh[mt], bfh[nt][2 * h], bfh[nt][2 * h + 1]);
                        MMA_BF16(c, afh[mt], bfl[nt][2 * h], bfl[nt][2 * h + 1]);
                        MMA_BF16(c, afl[mt], bfh[nt][2 * h], bfh[nt][2 * h + 1]);
                    }
        }
        if (ch + 1 < nch) {
            sts((ch + 1) & 1);
            __syncthreads();
        }
    }

    // epilogue: rows < 128 => At (channels 0,1,2); rows >= 128 => Bv (channel 3)
    const float* Cb = C + (size_t)zb * D_ * LC;
    const float* rv = rinv + zb * LC;
    float* O = out + (size_t)zb * 4 * D_ * LC;
#pragma unroll
    for (int mt = 0; mt < 4; mt++) {
        int r0 = wm + mt * 16 + (lane >> 2);
        int r1 = r0 + 8;
#pragma unroll
        for (int nt = 0; nt < 4; nt++) {
            int col = n0 + wn + nt * 8 + (lane & 3) * 2;
            float c0 = rv[col], c1v = rv[col + 1];
            float2 v0, v1;
            v0.x = acc[mt][nt][0] * c0; v0.y = acc[mt][nt][1] * c1v;
            v1.x = acc[mt][nt][2] * c0; v1.y = acc[mt][nt][3] * c1v;
            if (wm < 128) {
                int d0 = r0, d1 = r1;
                float2 cc0 = *reinterpret_cast<const float2*>(Cb + (size_t)d0 * LC + col);
                float2 cc1 = *reinterpret_cast<const float2*>(Cb + (size_t)d1 * LC + col);
                *reinterpret_cast<float2*>(O + (size_t)d0 * LC + col) = cc0;
                *reinterpret_cast<float2*>(O + (size_t)d1 * LC + col) = cc1;
                *reinterpret_cast<float2*>(O + (size_t)(D_ + d0) * LC + col) = v0;
                *reinterpret_cast<float2*>(O + (size_t)(D_ + d1) * LC + col) = v1;
                float2 m0v, m1v;
                m0v.x = cc0.x * v0.x; m0v.y = cc0.y * v0.y;
                m1v.x = cc1.x * v1.x; m1v.y = cc1.y * v1.y;
                *reinterpret_cast<float2*>(O + (size_t)(2 * D_ + d0) * LC + col) = m0v;
                *reinterpret_cast<float2*>(O + (size_t)(2 * D_ + d1) * LC + col) = m1v;
            } else {
                int d0 = r0 - 128, d1 = r1 - 128;
                float2 cc0 = *reinterpret_cast<const float2*>(Cb + (size_t)d0 * LC + col);
                float2 cc1 = *reinterpret_cast<const float2*>(Cb + (size_t)d1 * LC + col);
                float2 b0v, b1v;
                b0v.x = cc0.x * v0.x; b0v.y = cc0.y * v0.y;
                b1v.x = cc1.x * v1.x; b1v.y = cc1.y * v1.y;
                *reinterpret_cast<float2*>(O + (size_t)(3 * D_ + d0) * LC + col) = b0v;
                *reinterpret_cast<float2*>(O + (size_t)(3 * D_ + d1) * LC + col) = b1v;
            }
        }
    }
}

// ---------------- K1: bias vectors c1[l] = Ct.w1, q2[m] = Qt.w2 ----------------
__global__ void k_bias(const float* __restrict__ C, const float* __restrict__ Q,
                       const float* __restrict__ w) {
    int b = blockIdx.y, seg = blockIdx.x, t = threadIdx.x;
    if (seg < 4) {
        int l = seg * 256 + t;
        const float* Cb = C + (size_t)b * D_ * LC;
        float acc = 0.f;
#pragma unroll 8
        for (int d = 0; d < D_; d++) acc += Cb[(size_t)d * LC + l] * __ldg(w + d);
        g_c1[b * LC + l] = acc;
    } else {
        int m = t;
        const float* Qb = Q + (size_t)b * D_ * LQ;
        float acc = 0.f;
#pragma unroll 8
        for (int d = 0; d < D_; d++) acc += Qb[(size_t)d * LQ + m] * __ldg(w + D_ + d);
        g_q2[b * LQ + m] = acc;
    }
}

// ---------------- sums: rinv[l] = 1/sum_m E*qm, col partials for cinv ----------------
__global__ __launch_bounds__(256) void k_sums(const float* __restrict__ qmask,
                                              const float* __restrict__ cmask) {
    int b = blockIdx.y, rc = blockIdx.x;
    int w = threadIdx.x >> 5, lane = threadIdx.x & 31;
    __shared__ float cp[8][256];
    float4 q0 = *reinterpret_cast<const float4*>(qmask + b * LQ + lane * 4);
    float4 q1 = *reinterpret_cast<const float4*>(qmask + b * LQ + 128 + lane * 4);
    float col[8] = {0.f, 0.f, 0.f, 0.f, 0.f, 0.f, 0.f, 0.f};
#pragma unroll 4
    for (int rr = 0; rr < 16; rr++) {
        int l = rc * 128 + w * 16 + rr;
        const float* Er = g_E + ((size_t)b * LC + l) * LQ;
        float4 e0 = *reinterpret_cast<const float4*>(Er + lane * 4);
        float4 e1 = *reinterpret_cast<const float4*>(Er + 128 + lane * 4);
        float cm = cmask[b * LC + l];
        col[0] += e0.x * cm; col[1] += e0.y * cm; col[2] += e0.z * cm; col[3] += e0.w * cm;
        col[4] += e1.x * cm; col[5] += e1.y * cm; col[6] += e1.z * cm; col[7] += e1.w * cm;
        float s = e0.x * q0.x + e0.y * q0.y + e0.z * q0.z + e0.w * q0.w
                + e1.x * q1.x + e1.y * q1.y + e1.z * q1.z + e1.w * q1.w;
#pragma unroll
        for (int o = 16; o; o >>= 1) s += __shfl_xor_sync(0xffffffffu, s, o);
        if (lane == 0) g_rinv[b * LC + l] = 1.f / s;
    }
#pragma unroll
    for (int j = 0; j < 4; j++) {
        cp[w][lane * 4 + j] = col[j];
        cp[w][128 + lane * 4 + j] = col[4 + j];
    }
    __syncthreads();
    int m = threadIdx.x;
    float c = cp[0][m] + cp[1][m] + cp[2][m] + cp[3][m]
            + cp[4][m] + cp[5][m] + cp[6][m] + cp[7][m];
    g_cpart[(b * 8 + rc) * 256 + m] = c;
}

__global__ void k_colfin(const float* __restrict__ qmask) {
    int b = blockIdx.x, m = threadIdx.x;
    const float* p = g_cpart + b * 8 * 256 + m;
    float c = p[0] + p[256] + p[512] + p[768] + p[1024] + p[1280] + p[1536] + p[1792];
    g_qcinv[b * LQ + m] = qmask[b * LQ + m] / c;
}

// ---------------- launch ----------------
extern "C" void kernel_launch(void* const* d_in, const int* in_sizes, int n_in,
                              void* d_out, int out_size) {
    const float* C     = (const float*)d_in[0];
    const float* Q     = (const float*)d_in[1];
    const float* cmask = (const float*)d_in[2];
    const float* qmask = (const float*)d_in[3];
    const float* w     = (const float*)d_in[4];
    float* out = (float*)d_out;

    float *pE, *pT, *pc1, *pq2, *prv, *pqc;
    cudaGetSymbolAddress((void**)&pE,   g_E);
    cudaGetSymbolAddress((void**)&pT,   g_T);
    cudaGetSymbolAddress((void**)&pc1,  g_c1);
    cudaGetSymbolAddress((void**)&pq2,  g_q2);
    cudaGetSymbolAddress((void**)&prv,  g_rinv);
    cudaGetSymbolAddress((void**)&pqc,  g_qcinv);

    const int TG_SMEM  = 2 * 4 * 128 * LDS_ * 2;            // 81920 B
    const int G24_SMEM = 2 * (2 * 256 + 2 * 64) * LDS_ * 2; // 102400 B
    static int smem_set = 0;
    if (!smem_set) {
        cudaFuncSetAttribute(tgemm<true, true,  true,  false, 1>,
                             cudaFuncAttributeMaxDynamicSharedMemorySize, TG_SMEM);
        cudaFuncSetAttribute(tgemm<true, false, false, true,  0>,
                             cudaFuncAttributeMaxDynamicSharedMemorySize, TG_SMEM);
        cudaFuncSetAttribute(g24, cudaFuncAttributeMaxDynamicSharedMemorySize, G24_SMEM);
        smem_set = 1;
    }

    // 1: bias vectors
    k_bias<<<dim3(5, B_), 256>>>(C, Q, w);

    // 2: G1  E = exp((C*w3)^T Q + c1 + q2)   [m=l (8 tiles), n=m' (2), K=D]
    tgemm<true, true, true, false, 1><<<dim3(2, 8, B_), 256, TG_SMEM>>>(
        C, LC, (long)D_ * LC,  Q, LQ, (long)D_ * LQ,
        pE, LQ, (long)LC * LQ,  D_,
        w + 2 * D_, 0,  nullptr, 0,  pc1, pq2);

    // 3: sums -> rinv, col partials
    k_sums<<<dim3(8, B_), 256>>>(qmask, cmask);

    // 4 (profiled): G3  T_raw[m'][d] = sum_l E(l,m')*cm(l)*C(d,l)   [m=m' (2), n=d (1), K=Lc]
    tgemm<true, false, false, true, 0><<<dim3(1, 2, B_), 256, TG_SMEM>>>(
        pE, LQ, (long)LC * LQ,  C, LC, (long)D_ * LC,
        pT, D_, (long)LQ * D_,  LC,
        nullptr, 0,  cmask, LC,  nullptr, nullptr);

    // 5: qcinv[m'] = qm(m') / colsum(m')
    k_colfin<<<B_, 256>>>(qmask);

    // 6: fused G2+G4 + output assembly
    g24<<<dim3(LC / 64, 1, B_), 256, G24_SMEM>>>(
        Q, pT, pE, C, qmask, pqc, prv, out);
}

// round 11
// speedup vs baseline: 1.1221x; 1.1221x over previous
#include <cuda_runtime.h>
#include <cuda_bf16.h>
#include <cstdint>

#define B_  64
#define D_  128
#define LC  1024
#define LQ  256
#define FST 36       // fp32 smem row stride (144B: conflict-free STS.128 + ldmatrix)

// ---------------- scratch (static device arrays) ----------------
static __device__ float g_E   [(size_t)B_*LC*LQ];    // exp(S + biases), unnormalized
static __device__ float g_T   [(size_t)B_*LQ*D_];    // T_raw [m'][d] (unscaled)
static __device__ float g_rinv[B_*LC];
static __device__ float g_qcinv[B_*LQ];
static __device__ float g_cpart[B_*8*LQ];
static __device__ float g_c1[B_*LC];
static __device__ float g_q2[B_*LQ];

// ---------------- helpers ----------------
__device__ __forceinline__ uint32_t smem_u32(const void* p) {
    uint32_t a;
    asm("{ .reg .u64 t; cvta.to.shared.u64 t, %1; cvt.u32.u64 %0, t; }" : "=r"(a) : "l"(p));
    return a;
}

__device__ __forceinline__ float tf32r(float x) {
    uint32_t o; asm("cvt.rna.tf32.f32 %0, %1;" : "=r"(o) : "f"(x));
    return __uint_as_float(o);
}

#define LDSM_X4(r, a) \
    asm volatile("ldmatrix.sync.aligned.m8n8.x4.shared.b16 {%0,%1,%2,%3}, [%4];" \
        : "=r"((r)[0]), "=r"((r)[1]), "=r"((r)[2]), "=r"((r)[3]) : "r"(a))

#define MMA_TF32(c, a, b0, b1) \
    asm volatile("mma.sync.aligned.m16n8k8.row.col.f32.tf32.tf32.f32 " \
        "{%0,%1,%2,%3}, {%4,%5,%6,%7}, {%8,%9}, {%0,%1,%2,%3};" \
        : "+f"((c)[0]), "+f"((c)[1]), "+f"((c)[2]), "+f"((c)[3]) \
        : "r"((a)[0]), "r"((a)[1]), "r"((a)[2]), "r"((a)[3]), "r"(b0), "r"(b1))

// ---------------- operand loaders ----------------
// logical: element (mn, klocal) -> smem[mn*FST + klocal] (fp32, tf32-rounded)
template<bool TRANS, bool KS>
__device__ __forceinline__ void ldg_op(const float* __restrict__ src, int ld, int mn0,
                                       int kk, const float* __restrict__ ks,
                                       int tid, float4 (&r)[4]) {
#pragma unroll
    for (int i = 0; i < 4; i++) {
        int v = i * 256 + tid;
        if constexpr (!TRANS) {
            int row = v >> 3, c4 = v & 7;
            float4 x = *reinterpret_cast<const float4*>(src + (size_t)(mn0 + row) * ld + kk + c4 * 4);
            if constexpr (KS) {
                float4 s = *reinterpret_cast<const float4*>(ks + kk + c4 * 4);
                x.x *= s.x; x.y *= s.y; x.z *= s.z; x.w *= s.w;
            }
            r[i] = x;
        } else {
            int mn = v & 127, krb = v >> 7;
            const float* p = src + (size_t)(kk + krb * 4) * ld + mn0 + mn;
            float4 x;
            x.x = p[0]; x.y = p[ld]; x.z = p[2 * (size_t)ld]; x.w = p[3 * (size_t)ld];
            if constexpr (KS) {
                const float* s = ks + kk + krb * 4;
                x.x *= s[0]; x.y *= s[1]; x.z *= s[2]; x.w *= s[3];
            }
            r[i] = x;
        }
    }
}

template<bool TRANS>
__device__ __forceinline__ void sts_op(float4 (&r)[4], float* sm, int tid) {
#pragma unroll
    for (int i = 0; i < 4; i++) {
        int v = i * 256 + tid;
        int off;
        if constexpr (!TRANS) { int row = v >> 3, c4 = v & 7; off = row * FST + c4 * 4; }
        else                  { int mn = v & 127, krb = v >> 7; off = mn * FST + krb * 4; }
        float4 t;
        t.x = tf32r(r[i].x); t.y = tf32r(r[i].y);
        t.z = tf32r(r[i].z); t.w = tf32r(r[i].w);
        *reinterpret_cast<float4*>(sm + off) = t;
    }
}

// ---------------- single-pass tf32 tensor GEMM: Out(m,n) = sum_k A(m,k)*B(n,k) ----------------
// EPI 0: plain fp32 ; EPI 1: exp(acc + biasR[row] + biasC[col])
template<bool AT, bool BT, bool KSA, bool KSB, int EPI>
__global__ __launch_bounds__(256) void tgemm(
    const float* __restrict__ Ag, int lda, long batA,
    const float* __restrict__ Bg, int ldb, long batB,
    float* __restrict__ Cg, int ldc, long batC,
    int Kloc,
    const float* __restrict__ ksA, int ksAstr,
    const float* __restrict__ ksB, int ksBstr,
    const float* __restrict__ biasR, const float* __restrict__ biasC)
{
    __shared__ __align__(16) float sA[128 * FST];
    __shared__ __align__(16) float sB[128 * FST];

    const int zb = blockIdx.z;
    const int m0 = blockIdx.y << 7;
    const int n0 = blockIdx.x << 7;
    const float* Ab = Ag + (size_t)zb * batA;
    const float* Bb = Bg + (size_t)zb * batB;
    const float* kA = KSA ? (ksA + (size_t)zb * ksAstr) : nullptr;
    const float* kB = KSB ? (ksB + (size_t)zb * ksBstr) : nullptr;

    const int tid = threadIdx.x, wid = tid >> 5, lane = tid & 31;
    const int wm = (wid >> 2) * 64, wn = (wid & 3) * 32;

    float acc[4][4][4];
#pragma unroll
    for (int i = 0; i < 4; i++)
#pragma unroll
        for (int j = 0; j < 4; j++)
#pragma unroll
            for (int e = 0; e < 4; e++) acc[i][j][e] = 0.f;

    float4 ra[4], rb[4];
    const uint32_t bA = smem_u32(sA), bB = smem_u32(sB);
    const uint32_t lrow = (uint32_t)(lane & 15) * FST + ((lane >> 4) << 2);

    const int nch = Kloc >> 5;
    ldg_op<AT, KSA>(Ab, lda, m0, 0, kA, tid, ra);
    ldg_op<BT, KSB>(Bb, ldb, n0, 0, kB, tid, rb);

    for (int ch = 0; ch < nch; ch++) {
        sts_op<AT>(ra, sA, tid);
        sts_op<BT>(rb, sB, tid);
        __syncthreads();
        if (ch + 1 < nch) {
            int kk = (ch + 1) << 5;
            ldg_op<AT, KSA>(Ab, lda, m0, kk, kA, tid, ra);
            ldg_op<BT, KSB>(Bb, ldb, n0, kk, kB, tid, rb);
        }
#pragma unroll
        for (int ks = 0; ks < 4; ks++) {
            uint32_t af[4][4];
#pragma unroll
            for (int mt = 0; mt < 4; mt++) {
                uint32_t aoff = ((uint32_t)(wm + mt * 16) * FST + lrow + ks * 8) * 4u;
                LDSM_X4(af[mt], bA + aoff);
            }
            uint32_t bf[2][4];
#pragma unroll
            for (int nb = 0; nb < 2; nb++) {
                uint32_t boff = ((uint32_t)(wn + nb * 16) * FST + lrow + ks * 8) * 4u;
                LDSM_X4(bf[nb], bB + boff);
            }
#pragma unroll
            for (int mt = 0; mt < 4; mt++)
#pragma unroll
                for (int nb = 0; nb < 2; nb++) {
                    MMA_TF32(acc[mt][nb * 2 + 0], af[mt], bf[nb][0], bf[nb][2]);
                    MMA_TF32(acc[mt][nb * 2 + 1], af[mt], bf[nb][1], bf[nb][3]);
                }
        }
        __syncthreads();
    }

    float* Cb = Cg + (size_t)zb * batC;
#pragma unroll
    for (int mt = 0; mt < 4; mt++) {
        int r0 = m0 + wm + mt * 16 + (lane >> 2);
        int r1 = r0 + 8;
        float br0 = 0.f, br1 = 0.f;
        if constexpr (EPI == 1) { br0 = biasR[zb * LC + r0]; br1 = biasR[zb * LC + r1]; }
#pragma unroll
        for (int nt = 0; nt < 4; nt++) {
            int col = n0 + wn + nt * 8 + (lane & 3) * 2;
            float2 v0, v1;
            v0.x = acc[mt][nt][0]; v0.y = acc[mt][nt][1];
            v1.x = acc[mt][nt][2]; v1.y = acc[mt][nt][3];
            if constexpr (EPI == 1) {
                float bc0 = biasC[zb * LQ + col], bc1 = biasC[zb * LQ + col + 1];
                v0.x = __expf(v0.x + br0 + bc0); v0.y = __expf(v0.y + br0 + bc1);
                v1.x = __expf(v1.x + br1 + bc0); v1.y = __expf(v1.y + br1 + bc1);
            }
            *reinterpret_cast<float2*>(Cb + (size_t)r0 * ldc + col) = v0;
            *reinterpret_cast<float2*>(Cb + (size_t)r1 * ldc + col) = v1;
        }
    }
}

// ---------------- fused G2+G4: stacked A = [Q*qm ; T_raw*qcinv], B = E tile ----------------
__global__ __launch_bounds__(256) void g24(
    const float* __restrict__ Q, const float* __restrict__ T,
    const float* __restrict__ E, const float* __restrict__ C,
    const float* __restrict__ qmask, const float* __restrict__ qcinv,
    const float* __restrict__ rinv, float* __restrict__ out)
{
    __shared__ __align__(16) float sA[256 * FST];
    __shared__ __align__(16) float sB[64 * FST];

    const int zb = blockIdx.z;
    const int n0 = blockIdx.x * 64;
    const float* Qb = Q + (size_t)zb * D_ * LQ;
    const float* Tb = T + (size_t)zb * LQ * D_;
    const float* Eb = E + (size_t)zb * LC * LQ;
    const float* qm = qmask + zb * LQ;
    const float* qc = qcinv + zb * LQ;

    const int tid = threadIdx.x, wid = tid >> 5, lane = tid & 31;
    const int wm = (wid >> 1) * 64, wn = (wid & 1) * 32;

    float acc[4][4][4];
#pragma unroll
    for (int i = 0; i < 4; i++)
#pragma unroll
        for (int j = 0; j < 4; j++)
#pragma unroll
            for (int e = 0; e < 4; e++) acc[i][j][e] = 0.f;

    float4 ra[8], rb[2];

    auto ldgA = [&](int kk) {
#pragma unroll
        for (int i = 0; i < 4; i++) {                 // Q half, rows 0..127, K-fast
            int v = i * 256 + tid;
            int row = v >> 3, c4 = v & 7;
            float4 x = *reinterpret_cast<const float4*>(Qb + (size_t)row * LQ + kk + c4 * 4);
            float4 s = *reinterpret_cast<const float4*>(qm + kk + c4 * 4);
            x.x *= s.x; x.y *= s.y; x.z *= s.z; x.w *= s.w;
            ra[i] = x;
        }
#pragma unroll
        for (int i = 0; i < 4; i++) {                 // T half, rows 128..255, K-slow
            int v = i * 256 + tid;
            int mn = v & 127, krb = v >> 7;
            const float* p = Tb + (size_t)(kk + krb * 4) * D_ + mn;
            const float* s = qc + kk + krb * 4;
            float4 x;
            x.x = p[0] * s[0]; x.y = p[D_] * s[1];
            x.z = p[2 * D_] * s[2]; x.w = p[3 * D_] * s[3];
            ra[4 + i] = x;
        }
    };
    auto ldgB = [&](int kk) {
#pragma unroll
        for (int i = 0; i < 2; i++) {                 // E tile, 64 rows (l), K-fast
            int v = i * 256 + tid;
            int row = v >> 3, c4 = v & 7;
            rb[i] = *reinterpret_cast<const float4*>(Eb + (size_t)(n0 + row) * LQ + kk + c4 * 4);
        }
    };
    auto sts = [&]() {
#pragma unroll
        for (int i = 0; i < 4; i++) {
            int v = i * 256 + tid;
            int row = v >> 3, c4 = v & 7;
            float4 t;
            t.x = tf32r(ra[i].x); t.y = tf32r(ra[i].y);
            t.z = tf32r(ra[i].z); t.w = tf32r(ra[i].w);
            *reinterpret_cast<float4*>(sA + row * FST + c4 * 4) = t;
        }
#pragma unroll
        for (int i = 0; i < 4; i++) {
            int v = i * 256 + tid;
            int mn = v & 127, krb = v >> 7;
            float4 t;
            t.x = tf32r(ra[4 + i].x); t.y = tf32r(ra[4 + i].y);
            t.z = tf32r(ra[4 + i].z); t.w = tf32r(ra[4 + i].w);
            *reinterpret_cast<float4*>(sA + (128 + mn) * FST + krb * 4) = t;
        }
#pragma unroll
        for (int i = 0; i < 2; i++) {
            int v = i * 256 + tid;
            int row = v >> 3, c4 = v & 7;
            float4 t;
            t.x = tf32r(rb[i].x); t.y = tf32r(rb[i].y);
            t.z = tf32r(rb[i].z); t.w = tf32r(rb[i].w);
            *reinterpret_cast<float4*>(sB + row * FST + c4 * 4) = t;
        }
    };

    const uint32_t bA = smem_u32(sA), bB = smem_u32(sB);
    const uint32_t lrow = (uint32_t)(lane & 15) * FST + ((lane >> 4) << 2);

    const int nch = LQ >> 5;   // 8
    ldgA(0); ldgB(0);

    for (int ch = 0; ch < nch; ch++) {
        sts();
        __syncthreads();
        if (ch + 1 < nch) { ldgA((ch + 1) << 5); ldgB((ch + 1) << 5); }
#pragma unroll
        for (int ks = 0; ks < 4; ks++) {
            uint32_t af[4][4];
#pragma unroll
            for (int mt = 0; mt < 4; mt++) {
                uint32_t aoff = ((uint32_t)(wm + mt * 16) * FST + lrow + ks * 8) * 4u;
                LDSM_X4(af[mt], bA + aoff);
            }
            uint32_t bf[2][4];
#pragma unroll
            for (int nb = 0; nb < 2; nb++) {
                uint32_t boff = ((uint32_t)(wn + nb * 16) * FST + lrow + ks * 8) * 4u;
                LDSM_X4(bf[nb], bB + boff);
            }
#pragma unroll
            for (int mt = 0; mt < 4; mt++)
#pragma unroll
                for (int nb = 0; nb < 2; nb++) {
                    MMA_TF32(acc[mt][nb * 2 + 0], af[mt], bf[nb][0], bf[nb][2]);
                    MMA_TF32(acc[mt][nb * 2 + 1], af[mt], bf[nb][1], bf[nb][3]);
                }
        }
        __syncthreads();
    }

    // epilogue: rows < 128 => At (channels 0,1,2); rows >= 128 => Bv (channel 3)
    const float* Cb = C + (size_t)zb * D_ * LC;
    const float* rv = rinv + zb * LC;
    float* O = out + (size_t)zb * 4 * D_ * LC;
#pragma unroll
    for (int mt = 0; mt < 4; mt++) {
        int r0 = wm + mt * 16 + (lane >> 2);
        int r1 = r0 + 8;
#pragma unroll
        for (int nt = 0; nt < 4; nt++) {
            int col = n0 + wn + nt * 8 + (lane & 3) * 2;
            float c0 = rv[col], c1v = rv[col + 1];
            float2 v0, v1;
            v0.x = acc[mt][nt][0] * c0; v0.y = acc[mt][nt][1] * c1v;
            v1.x = acc[mt][nt][2] * c0; v1.y = acc[mt][nt][3] * c1v;
            if (wm < 128) {
                int d0 = r0, d1 = r1;
                float2 cc0 = *reinterpret_cast<const float2*>(Cb + (size_t)d0 * LC + col);
                float2 cc1 = *reinterpret_cast<const float2*>(Cb + (size_t)d1 * LC + col);
                *reinterpret_cast<float2*>(O + (size_t)d0 * LC + col) = cc0;
                *reinterpret_cast<float2*>(O + (size_t)d1 * LC + col) = cc1;
                *reinterpret_cast<float2*>(O + (size_t)(D_ + d0) * LC + col) = v0;
                *reinterpret_cast<float2*>(O + (size_t)(D_ + d1) * LC + col) = v1;
                float2 m0v, m1v;
                m0v.x = cc0.x * v0.x; m0v.y = cc0.y * v0.y;
                m1v.x = cc1.x * v1.x; m1v.y = cc1.y * v1.y;
                *reinterpret_cast<float2*>(O + (size_t)(2 * D_ + d0) * LC + col) = m0v;
                *reinterpret_cast<float2*>(O + (size_t)(2 * D_ + d1) * LC + col) = m1v;
            } else {
                int d0 = r0 - 128, d1 = r1 - 128;
                float2 cc0 = *reinterpret_cast<const float2*>(Cb + (size_t)d0 * LC + col);
                float2 cc1 = *reinterpret_cast<const float2*>(Cb + (size_t)d1 * LC + col);
                float2 b0v, b1v;
                b0v.x = cc0.x * v0.x; b0v.y = cc0.y * v0.y;
                b1v.x = cc1.x * v1.x; b1v.y = cc1.y * v1.y;
                *reinterpret_cast<float2*>(O + (size_t)(3 * D_ + d0) * LC + col) = b0v;
                *reinterpret_cast<float2*>(O + (size_t)(3 * D_ + d1) * LC + col) = b1v;
            }
        }
    }
}

// ---------------- K1: bias vectors c1[l] = Ct.w1, q2[m] = Qt.w2 ----------------
__global__ void k_bias(const float* __restrict__ C, const float* __restrict__ Q,
                       const float* __restrict__ w) {
    int b = blockIdx.y, seg = blockIdx.x, t = threadIdx.x;
    if (seg < 4) {
        int l = seg * 256 + t;
        const float* Cb = C + (size_t)b * D_ * LC;
        float acc = 0.f;
#pragma unroll 8
        for (int d = 0; d < D_; d++) acc += Cb[(size_t)d * LC + l] * __ldg(w + d);
        g_c1[b * LC + l] = acc;
    } else {
        int m = t;
        const float* Qb = Q + (size_t)b * D_ * LQ;
        float acc = 0.f;
#pragma unroll 8
        for (int d = 0; d < D_; d++) acc += Qb[(size_t)d * LQ + m] * __ldg(w + D_ + d);
        g_q2[b * LQ + m] = acc;
    }
}

// ---------------- sums: rinv[l] = 1/sum_m E*qm, col partials for cinv ----------------
__global__ __launch_bounds__(256) void k_sums(const float* __restrict__ qmask,
                                              const float* __restrict__ cmask) {
    int b = blockIdx.y, rc = blockIdx.x;
    int w = threadIdx.x >> 5, lane = threadIdx.x & 31;
    __shared__ float cp[8][256];
    float4 q0 = *reinterpret_cast<const float4*>(qmask + b * LQ + lane * 4);
    float4 q1 = *reinterpret_cast<const float4*>(qmask + b * LQ + 128 + lane * 4);
    float col[8] = {0.f, 0.f, 0.f, 0.f, 0.f, 0.f, 0.f, 0.f};
#pragma unroll 4
    for (int rr = 0; rr < 16; rr++) {
        int l = rc * 128 + w * 16 + rr;
        const float* Er = g_E + ((size_t)b * LC + l) * LQ;
        float4 e0 = *reinterpret_cast<const float4*>(Er + lane * 4);
        float4 e1 = *reinterpret_cast<const float4*>(Er + 128 + lane * 4);
        float cm = cmask[b * LC + l];
        col[0] += e0.x * cm; col[1] += e0.y * cm; col[2] += e0.z * cm; col[3] += e0.w * cm;
        col[4] += e1.x * cm; col[5] += e1.y * cm; col[6] += e1.z * cm; col[7] += e1.w * cm;
        float s = e0.x * q0.x + e0.y * q0.y + e0.z * q0.z + e0.w * q0.w
                + e1.x * q1.x + e1.y * q1.y + e1.z * q1.z + e1.w * q1.w;
#pragma unroll
        for (int o = 16; o; o >>= 1) s += __shfl_xor_sync(0xffffffffu, s, o);
        if (lane == 0) g_rinv[b * LC + l] = 1.f / s;
    }
#pragma unroll
    for (int j = 0; j < 4; j++) {
        cp[w][lane * 4 + j] = col[j];
        cp[w][128 + lane * 4 + j] = col[4 + j];
    }
    __syncthreads();
    int m = threadIdx.x;
    float c = cp[0][m] + cp[1][m] + cp[2][m] + cp[3][m]
            + cp[4][m] + cp[5][m] + cp[6][m] + cp[7][m];
    g_cpart[(b * 8 + rc) * 256 + m] = c;
}

__global__ void k_colfin(const float* __restrict__ qmask) {
    int b = blockIdx.x, m = threadIdx.x;
    const float* p = g_cpart + b * 8 * 256 + m;
    float c = p[0] + p[256] + p[512] + p[768] + p[1024] + p[1280] + p[1536] + p[1792];
    g_qcinv[b * LQ + m] = qmask[b * LQ + m] / c;
}

// ---------------- launch ----------------
extern "C" void kernel_launch(void* const* d_in, const int* in_sizes, int n_in,
                              void* d_out, int out_size) {
    const float* C     = (const float*)d_in[0];
    const float* Q     = (const float*)d_in[1];
    const float* cmask = (const float*)d_in[2];
    const float* qmask = (const float*)d_in[3];
    const float* w     = (const float*)d_in[4];
    float* out = (float*)d_out;

    float *pE, *pT, *pc1, *pq2, *prv, *pqc;
    cudaGetSymbolAddress((void**)&pE,   g_E);
    cudaGetSymbolAddress((void**)&pT,   g_T);
    cudaGetSymbolAddress((void**)&pc1,  g_c1);
    cudaGetSymbolAddress((void**)&pq2,  g_q2);
    cudaGetSymbolAddress((void**)&prv,  g_rinv);
    cudaGetSymbolAddress((void**)&pqc,  g_qcinv);

    // 1: bias vectors
    k_bias<<<dim3(5, B_), 256>>>(C, Q, w);

    // 2: G1  E = exp((C*w3)^T Q + c1 + q2)   [m=l (8 tiles), n=m' (2), K=D]
    tgemm<true, true, true, false, 1><<<dim3(2, 8, B_), 256>>>(
        C, LC, (long)D_ * LC,  Q, LQ, (long)D_ * LQ,
        pE, LQ, (long)LC * LQ,  D_,
        w + 2 * D_, 0,  nullptr, 0,  pc1, pq2);

    // 3: sums -> rinv, col partials
    k_sums<<<dim3(8, B_), 256>>>(qmask, cmask);

    // 4 (profiled): G3  T_raw[m'][d] = sum_l E(l,m')*cm(l)*C(d,l)   [m=m' (2), n=d (1), K=Lc]
    tgemm<true, false, false, true, 0><<<dim3(1, 2, B_), 256>>>(
        pE, LQ, (long)LC * LQ,  C, LC, (long)D_ * LC,
        pT, D_, (long)LQ * D_,  LC,
        nullptr, 0,  cmask, LC,  nullptr, nullptr);

    // 5: qcinv[m'] = qm(m') / colsum(m')
    k_colfin<<<B_, 256>>>(qmask);

    // 6: fused G2+G4 + output assembly
    g24<<<dim3(LC / 64, 1, B_), 256>>>(
        Q, pT, pE, C, qmask, pqc, prv, out);
}